// round 7
// baseline (speedup 1.0000x reference)
#include <cuda_runtime.h>
#include <cuda_bf16.h>
#include <math.h>

#define BB 2
#define SSEQ 4096
#define NH 8
#define DHEAD 64
#define HD 512
#define LM 128
#define WWIN 128
#define EXTW 64
#define HL 1024
#define NKEY 384
#define QT 32

// ---------------- scratch (device globals; no allocations) ----------------
__device__ float g_Q [BB*SSEQ*HD];
__device__ float g_K [BB*SSEQ*HD];
__device__ float g_V [BB*SSEQ*HD];
__device__ float g_Dl[BB*SSEQ*HL];   // D logits, softmaxed in-place -> hs
__device__ float g_Kc[BB*LM*HD];
__device__ float g_Vc[BB*LM*HD];

// bf16 arena: X hi/lo, C hi/lo, transposed-weight hi/lo
#define XHI  0
#define XLO  4194304
#define CHI  8388608
#define CLO  12582912
#define WQTH 16777216
#define WQTL 17039360
#define WKTH 17301504
#define WKTL 17563648
#define WVTH 17825792
#define WVTL 18087936
#define WDTH 18350080
#define WDTL 18874368
#define WOTH 19398656
#define WOTL 19660800
__device__ __nv_bfloat16 g_bf[19922944];

// ================= helpers =================
__device__ __forceinline__ unsigned smem_u32(const void* p) {
    unsigned a;
    asm("{ .reg .u64 t; cvta.to.shared.u64 t, %1; cvt.u32.u64 %0, t; }" : "=r"(a) : "l"(p));
    return a;
}
__device__ __forceinline__ unsigned swz(unsigned b) { return b ^ ((b >> 3) & 0x70u); }

__device__ __forceinline__ void ldsm_x4(unsigned* r, unsigned addr) {
    asm volatile("ldmatrix.sync.aligned.m8n8.x4.shared.b16 {%0,%1,%2,%3}, [%4];"
        : "=r"(r[0]),"=r"(r[1]),"=r"(r[2]),"=r"(r[3]) : "r"(addr));
}
__device__ __forceinline__ void ldsm_x2(unsigned* r, unsigned addr) {
    asm volatile("ldmatrix.sync.aligned.m8n8.x2.shared.b16 {%0,%1}, [%2];"
        : "=r"(r[0]),"=r"(r[1]) : "r"(addr));
}
__device__ __forceinline__ void mma16816(float* c, const unsigned* a, const unsigned* b) {
    asm volatile("mma.sync.aligned.m16n8k16.row.col.f32.bf16.bf16.f32 "
        "{%0,%1,%2,%3}, {%4,%5,%6,%7}, {%8,%9}, {%0,%1,%2,%3};"
        : "+f"(c[0]),"+f"(c[1]),"+f"(c[2]),"+f"(c[3])
        : "r"(a[0]),"r"(a[1]),"r"(a[2]),"r"(a[3]), "r"(b[0]),"r"(b[1]));
}

// ================= bf16-split conversion kernels =================
__global__ __launch_bounds__(256) void split_kernel(
    const float* __restrict__ src, __nv_bfloat16* __restrict__ hi,
    __nv_bfloat16* __restrict__ lo, int n)
{
    int i = (blockIdx.x * 256 + threadIdx.x) * 8;
    if (i >= n) return;
    #pragma unroll
    for (int j = 0; j < 8; j += 4) {
        float4 v = *(const float4*)(src + i + j);
        __nv_bfloat16 h0 = __float2bfloat16(v.x);
        __nv_bfloat16 h1 = __float2bfloat16(v.y);
        __nv_bfloat16 h2 = __float2bfloat16(v.z);
        __nv_bfloat16 h3 = __float2bfloat16(v.w);
        __nv_bfloat16 l0 = __float2bfloat16(v.x - __bfloat162float(h0));
        __nv_bfloat16 l1 = __float2bfloat16(v.y - __bfloat162float(h1));
        __nv_bfloat16 l2 = __float2bfloat16(v.z - __bfloat162float(h2));
        __nv_bfloat16 l3 = __float2bfloat16(v.w - __bfloat162float(h3));
        *(__nv_bfloat162*)(hi + i + j)     = __halves2bfloat162(h0, h1);
        *(__nv_bfloat162*)(hi + i + j + 2) = __halves2bfloat162(h2, h3);
        *(__nv_bfloat162*)(lo + i + j)     = __halves2bfloat162(l0, l1);
        *(__nv_bfloat162*)(lo + i + j + 2) = __halves2bfloat162(l2, l3);
    }
}

// W [512, N] fp32 -> T hi/lo [N, 512] bf16
__global__ __launch_bounds__(256) void transpose_split_kernel(
    const float* __restrict__ W, __nv_bfloat16* __restrict__ Thi,
    __nv_bfloat16* __restrict__ Tlo, int N)
{
    __shared__ float tile[32][33];
    int n0 = blockIdx.x * 32, k0 = blockIdx.y * 32;
    int tx = threadIdx.x, ty = threadIdx.y;
    #pragma unroll
    for (int i = 0; i < 32; i += 8)
        tile[ty + i][tx] = W[(size_t)(k0 + ty + i) * N + n0 + tx];
    __syncthreads();
    #pragma unroll
    for (int i = 0; i < 32; i += 8) {
        float x = tile[tx][ty + i];
        __nv_bfloat16 h = __float2bfloat16(x);
        __nv_bfloat16 l = __float2bfloat16(x - __bfloat162float(h));
        size_t o = (size_t)(n0 + ty + i) * 512 + k0 + tx;
        Thi[o] = h; Tlo[o] = l;
    }
}

// ================= bf16-split GEMM on mma.sync (HMMA) =================
// C[M=8192, N] = alpha * (A[M,512] @ Bt^T + bias); Bt stored [N,512] K-major bf16.
// 24 K-chunks of 64: chunks 0-7 = Ah*Bh, 8-15 = Ah*Bl, 16-23 = Al*Bh.
// Tile 128x128, 8 warps (2x4), warp tile 64x32 = 4x4 m16n8k16.
// smem per stage: A 16KB + B 16KB (SW128 swizzled rows of 128B), 2 stages = 64KB.
__device__ __forceinline__ void gemm_compute_stage(
    unsigned sb, int st, int wm, int wn, int lane, float acc[4][4][4])
{
    const unsigned sA = sb + (unsigned)st * 32768u;
    const unsigned sB = sA + 16384u;
    const int la = lane & 15;
    #pragma unroll
    for (int ks = 0; ks < 4; ++ks) {
        unsigned a[4][4], b[4][2];
        #pragma unroll
        for (int ma = 0; ma < 4; ++ma) {
            unsigned arow = (unsigned)(wm*64 + ma*16 + la);
            unsigned ab   = (unsigned)(ks*32 + ((lane>>4)&1)*16);
            ldsm_x4(a[ma], sA + swz(arow*128u + ab));
        }
        #pragma unroll
        for (int na = 0; na < 4; ++na) {
            unsigned brow = (unsigned)(wn*32 + na*8 + (la & 7));
            unsigned bb   = (unsigned)(ks*32 + ((la>>3)&1)*16);
            ldsm_x2(b[na], sB + swz(brow*128u + bb));
        }
        #pragma unroll
        for (int ma = 0; ma < 4; ++ma)
            #pragma unroll
            for (int na = 0; na < 4; ++na)
                mma16816(acc[ma][na], a[ma], b[na]);
    }
}

__global__ __launch_bounds__(256) void gemm_mma_kernel(
    const __nv_bfloat16* __restrict__ Ahi, const __nv_bfloat16* __restrict__ Alo,
    const __nv_bfloat16* __restrict__ Bhi, const __nv_bfloat16* __restrict__ Blo,
    const float* __restrict__ bias, float* __restrict__ C, int N, float alpha)
{
    extern __shared__ __align__(128) char smem[];
    const unsigned sb = smem_u32(smem);
    const int tid  = threadIdx.x;
    const int lane = tid & 31, wid = tid >> 5;
    const int wm = wid >> 2, wn = wid & 3;
    const int bm = blockIdx.y, bn = blockIdx.x;

    float acc[4][4][4];
    #pragma unroll
    for (int i=0;i<4;i++)
        #pragma unroll
        for (int j=0;j<4;j++)
            #pragma unroll
            for (int k=0;k<4;k++) acc[i][j][k]=0.f;

#define LDCH(rg, c) { \
    const __nv_bfloat16* As = ((c) >= 16) ? Alo : Ahi; \
    const __nv_bfloat16* Bs = ((c) >= 8 && (c) < 16) ? Blo : Bhi; \
    const int kc = (c) & 7; \
    _Pragma("unroll") \
    for (int i = 0; i < 4; ++i) { \
        int e = i*256 + tid; int r = e >> 3, u = e & 7; \
        (rg)[i]   = *(const uint4*)(As + (size_t)(bm*128 + r)*512 + kc*64 + u*8); \
        (rg)[4+i] = *(const uint4*)(Bs + (size_t)(bn*128 + r)*512 + kc*64 + u*8); \
    } }
#define STCH(st, rg) { \
    const unsigned base = (unsigned)(st) * 32768u; \
    _Pragma("unroll") \
    for (int i = 0; i < 4; ++i) { \
        int e = i*256 + tid; int r = e >> 3, u = e & 7; \
        unsigned off = swz((unsigned)(r*128 + u*16)); \
        *(uint4*)(smem + base + off)          = (rg)[i]; \
        *(uint4*)(smem + base + 16384u + off) = (rg)[4+i]; \
    } }

    {
        uint4 rg[8];
        LDCH(rg, 0);
        STCH(0, rg);
    }
    __syncthreads();

    for (int c = 0; c < 24; ++c) {
        uint4 rn[8];
        if (c < 23) LDCH(rn, c + 1);
        gemm_compute_stage(sb, c & 1, wm, wn, lane, acc);
        if (c < 23) STCH((c + 1) & 1, rn);
        __syncthreads();
    }
#undef LDCH
#undef STCH

    // epilogue: out = alpha * (acc + bias)
    #pragma unroll
    for (int ma = 0; ma < 4; ++ma) {
        const int row = bm*128 + wm*64 + ma*16 + (lane >> 2);
        #pragma unroll
        for (int na = 0; na < 4; ++na) {
            const int col = bn*128 + wn*32 + na*8 + (lane & 3)*2;
            const float b0 = bias[col], b1 = bias[col+1];
            float2 o0, o1;
            o0.x = alpha*(acc[ma][na][0] + b0);
            o0.y = alpha*(acc[ma][na][1] + b1);
            o1.x = alpha*(acc[ma][na][2] + b0);
            o1.y = alpha*(acc[ma][na][3] + b1);
            *(float2*)(C + (size_t)row*N + col)       = o0;
            *(float2*)(C + (size_t)(row+8)*N + col)   = o1;
        }
    }
}

// ---------------- LayerNorm over rows of 512 (in-place) ----------------
__global__ __launch_bounds__(128) void ln512_kernel(
    float* __restrict__ Y, const float* __restrict__ gam, const float* __restrict__ bet)
{
    const int row = blockIdx.x;
    float* x = Y + (size_t)row * HD;
    const int t = threadIdx.x;
    float4 v = *(float4*)(x + t*4);
    float s  = v.x+v.y+v.z+v.w;
    float ss = v.x*v.x + v.y*v.y + v.z*v.z + v.w*v.w;
    #pragma unroll
    for (int o=16;o>0;o>>=1) {
        s  += __shfl_xor_sync(0xffffffffu, s, o);
        ss += __shfl_xor_sync(0xffffffffu, ss, o);
    }
    __shared__ float rs[4], rss[4];
    if ((t&31)==0) { rs[t>>5]=s; rss[t>>5]=ss; }
    __syncthreads();
    s  = rs[0]+rs[1]+rs[2]+rs[3];
    ss = rss[0]+rss[1]+rss[2]+rss[3];
    const float mean = s * (1.f/HD);
    const float var  = ss*(1.f/HD) - mean*mean;
    const float inv  = rsqrtf(var + 1e-5f);
    float4 g4 = *(const float4*)(gam + t*4);
    float4 b4 = *(const float4*)(bet + t*4);
    v.x = (v.x-mean)*inv*g4.x + b4.x;
    v.y = (v.y-mean)*inv*g4.y + b4.y;
    v.z = (v.z-mean)*inv*g4.z + b4.z;
    v.w = (v.w-mean)*inv*g4.w + b4.w;
    *(float4*)(x + t*4) = v;
}

// ---------------- softmax over sequence axis of g_Dl (B,S,HL), in-place ----------------
__global__ void softmax_seq_kernel()
{
    const int b = blockIdx.y;
    const int j = blockIdx.x*32 + threadIdx.x;
    const int ty = threadIdx.y;
    float m = -3.0e38f;
    for (int s = ty; s < SSEQ; s += 32)
        m = fmaxf(m, g_Dl[(size_t)(b*SSEQ+s)*HL + j]);
    __shared__ float sM[32][33];
    __shared__ float sS[32][33];
    sM[ty][threadIdx.x] = m;
    __syncthreads();
    float M = -3.0e38f;
    #pragma unroll
    for (int i=0;i<32;i++) M = fmaxf(M, sM[i][threadIdx.x]);
    float ssum = 0.f;
    for (int s = ty; s < SSEQ; s += 32)
        ssum += __expf(g_Dl[(size_t)(b*SSEQ+s)*HL + j] - M);
    sS[ty][threadIdx.x] = ssum;
    __syncthreads();
    float tot = 0.f;
    #pragma unroll
    for (int i=0;i<32;i++) tot += sS[i][threadIdx.x];
    const float inv = 1.f / tot;
    for (int s = ty; s < SSEQ; s += 32) {
        size_t off = (size_t)(b*SSEQ+s)*HL + j;
        g_Dl[off] = __expf(g_Dl[off] - M) * inv;
    }
}

// ---------------- zero Kc/Vc ----------------
__global__ void zero_kv_kernel()
{
    int i = blockIdx.x*256 + threadIdx.x;
    if (i < BB*LM*HD) { g_Kc[i]=0.f; g_Vc[i]=0.f; }
}

// ---------------- Kc = hs^T @ K, Vc = hs^T @ V (per b,h), split-K=8 with atomics ----------------
__global__ __launch_bounds__(256) void landmark_kv_kernel()
{
    const int b = blockIdx.x >> 3;
    const int h = blockIdx.x & 7;
    const int s0 = blockIdx.y * (SSEQ/8);
    __shared__ float sh[8][128];
    __shared__ float sk[8][64];
    __shared__ float sv[8][64];
    const int t = threadIdx.x;
    const int d  = t & 63;
    const int lg = t >> 6;
    float aK[32], aV[32];
    #pragma unroll
    for (int i=0;i<32;i++){aK[i]=0.f;aV[i]=0.f;}

    for (int sc = 0; sc < SSEQ/8; sc += 8) {
        #pragma unroll
        for (int u = 0; u < 8; ++u) {
            int idx = u*256 + t;
            int si = idx >> 8;
            int c  = idx & 255;
            int s  = s0 + sc + si;
            if (c < 128)      sh[si][c]     = g_Dl[(size_t)(b*SSEQ+s)*HL + h*LM + c];
            else if (c < 192) sk[si][c-128] = g_K [(size_t)(b*SSEQ+s)*HD + h*DHEAD + (c-128)];
            else              sv[si][c-192] = g_V [(size_t)(b*SSEQ+s)*HD + h*DHEAD + (c-192)];
        }
        __syncthreads();
        #pragma unroll
        for (int si=0; si<8; ++si) {
            const float kv = sk[si][d];
            const float vv = sv[si][d];
            const float4* hp = (const float4*)&sh[si][lg*32];
            #pragma unroll
            for (int i4=0;i4<8;i4++){
                float4 h4 = hp[i4];
                aK[i4*4+0] += h4.x*kv; aV[i4*4+0] += h4.x*vv;
                aK[i4*4+1] += h4.y*kv; aV[i4*4+1] += h4.y*vv;
                aK[i4*4+2] += h4.z*kv; aV[i4*4+2] += h4.z*vv;
                aK[i4*4+3] += h4.w*kv; aV[i4*4+3] += h4.w*vv;
            }
        }
        __syncthreads();
    }
    #pragma unroll
    for (int i=0;i<32;i++){
        const int l = lg*32 + i;
        atomicAdd(&g_Kc[(size_t)(b*LM+l)*HD + h*DHEAD + d], aK[i]);
        atomicAdd(&g_Vc[(size_t)(b*LM+l)*HD + h*DHEAD + d], aV[i]);
    }
}

// ---------------- fused attention (register-tiled): 384 keys, softmax, PV ----------------
// Grid (S/32, H, B), 256 threads. Warp = 4 consecutive queries (broadcast Q/P loads).
// Score: thread computes 4q x 4k (keys lane+32j), 3 rounds of 128 keys.
// PV:    thread computes 4q x 2d (d = lane*2), 3 rounds of 128 keys.
// Epilogue writes bf16 hi/lo split of C directly.
__global__ __launch_bounds__(256) void attn_kernel(
    const int* __restrict__ mask,
    __nv_bfloat16* __restrict__ Chi, __nv_bfloat16* __restrict__ Clo)
{
    extern __shared__ float smemf[];
    float* Qs  = smemf;              // 32*68
    float* Sc  = Qs + 32*68;         // 32*385
    float* KVs = Sc + 32*385;        // 128*68
    __shared__ int vld[128];

    const int b  = blockIdx.z;
    const int h  = blockIdx.y;
    const int q0 = blockIdx.x * QT;
    const int g  = q0 >> 7;
    const int t  = threadIdx.x;
    const int tq   = t >> 5;         // warp id: queries tq*4 .. tq*4+3
    const int lane = t & 31;

    // load Q tile (32 x 64), row stride 68
    #pragma unroll
    for (int u = 0; u < 2; ++u) {
        int idx = u*256 + t;         // 512 float4
        int q = idx >> 4, c = idx & 15;
        *(float4*)&Qs[q*68 + c*4] =
            *(const float4*)&g_Q[(size_t)(b*SSEQ+q0+q)*HD + h*DHEAD + c*4];
    }

    // ---- score rounds: r=0 center (Kc), r=1,2 window (K) ----
    for (int r = 0; r < 3; ++r) {
        __syncthreads();
        if (t < 128) {
            int k = r*128 + t;
            int ok = 1;
            if (k >= 128) {
                int p = g*WWIN - EXTW + (k - 128);
                ok = (p >= 0 && p < SSEQ) ? (mask[b*SSEQ+p] != 0) : 0;
            }
            vld[t] = ok;
        }
        #pragma unroll
        for (int u = 0; u < 8; ++u) {
            int idx = u*256 + t;     // 2048 float4
            int kk = idx >> 4, c = idx & 15;
            int k = r*128 + kk;
            float4 val = make_float4(0.f,0.f,0.f,0.f);
            if (k < 128) {
                val = *(const float4*)&g_Kc[(size_t)(b*LM+k)*HD + h*DHEAD + c*4];
            } else {
                int p = g*WWIN - EXTW + (k-128);
                if (p >= 0 && p < SSEQ)
                    val = *(const float4*)&g_K[(size_t)(b*SSEQ+p)*HD + h*DHEAD + c*4];
            }
            *(float4*)&KVs[kk*68 + c*4] = val;
        }
        __syncthreads();

        float acc[4][4];
        #pragma unroll
        for (int i=0;i<4;i++)
            #pragma unroll
            for (int j=0;j<4;j++) acc[i][j]=0.f;

        #pragma unroll
        for (int d4 = 0; d4 < 16; ++d4) {
            float4 qv[4];
            #pragma unroll
            for (int i=0;i<4;i++) qv[i] = *(const float4*)&Qs[(tq*4+i)*68 + d4*4];
            #pragma unroll
            for (int j=0;j<4;j++) {
                float4 kv = *(const float4*)&KVs[(lane + 32*j)*68 + d4*4];
                #pragma unroll
                for (int i=0;i<4;i++)
                    acc[i][j] += qv[i].x*kv.x + qv[i].y*kv.y + qv[i].z*kv.z + qv[i].w*kv.w;
            }
        }
        #pragma unroll
        for (int j=0;j<4;j++) {
            int kk = lane + 32*j;
            int k  = r*128 + kk;
            int ok = vld[kk];
            #pragma unroll
            for (int i=0;i<4;i++)
                Sc[(tq*4+i)*385 + k] = ok ? acc[i][j] : -3.0e38f;
        }
    }
    __syncthreads();

    // ---- softmax over 384 keys per query row (8 lanes per row) ----
    {
        const int qg = t >> 3;
        const int kb = t & 7;
        float m = -3.0e38f;
        for (int k=kb; k<NKEY; k+=8) m = fmaxf(m, Sc[qg*385+k]);
        #pragma unroll
        for (int o=4;o>0;o>>=1) m = fmaxf(m, __shfl_xor_sync(0xffffffffu, m, o));
        float ssum = 0.f;
        for (int k=kb; k<NKEY; k+=8) {
            float e = __expf(Sc[qg*385+k] - m);
            Sc[qg*385+k] = e;
            ssum += e;
        }
        #pragma unroll
        for (int o=4;o>0;o>>=1) ssum += __shfl_xor_sync(0xffffffffu, ssum, o);
        float inv = (mask[b*SSEQ+q0+qg] != 0) ? (1.f/ssum) : 0.f;
        for (int k=kb; k<NKEY; k+=8) Sc[qg*385+k] *= inv;
    }

    // ---- PV rounds: thread owns 4q x 2d (d = lane*2, lane*2+1) ----
    float accp[4][2];
    #pragma unroll
    for (int i=0;i<4;i++){ accp[i][0]=0.f; accp[i][1]=0.f; }

    for (int r = 0; r < 3; ++r) {
        __syncthreads();
        #pragma unroll
        for (int u = 0; u < 8; ++u) {
            int idx = u*256 + t;
            int kk = idx >> 4, c = idx & 15;
            int k = r*128 + kk;
            float4 val = make_float4(0.f,0.f,0.f,0.f);
            if (k < 128) {
                val = *(const float4*)&g_Vc[(size_t)(b*LM+k)*HD + h*DHEAD + c*4];
            } else {
                int p = g*WWIN - EXTW + (k-128);
                if (p >= 0 && p < SSEQ)
                    val = *(const float4*)&g_V[(size_t)(b*SSEQ+p)*HD + h*DHEAD + c*4];
            }
            *(float4*)&KVs[kk*68 + c*4] = val;
        }
        __syncthreads();

        const int kbase = r*128;
        #pragma unroll 4
        for (int kk = 0; kk < 128; ++kk) {
            float2 vv = *(const float2*)&KVs[kk*68 + lane*2];
            #pragma unroll
            for (int i=0;i<4;i++) {
                float p = Sc[(tq*4+i)*385 + kbase + kk];
                accp[i][0] += p*vv.x;
                accp[i][1] += p*vv.y;
            }
        }
    }

    // ---- epilogue: write bf16 hi/lo split of C ----
    #pragma unroll
    for (int i=0;i<4;i++) {
        size_t off = (size_t)(b*SSEQ + q0 + tq*4 + i)*HD + h*DHEAD + lane*2;
        float x0 = accp[i][0], x1 = accp[i][1];
        __nv_bfloat16 h0 = __float2bfloat16(x0);
        __nv_bfloat16 h1 = __float2bfloat16(x1);
        __nv_bfloat16 l0 = __float2bfloat16(x0 - __bfloat162float(h0));
        __nv_bfloat16 l1 = __float2bfloat16(x1 - __bfloat162float(h1));
        *(__nv_bfloat162*)(Chi + off) = __halves2bfloat162(h0, h1);
        *(__nv_bfloat162*)(Clo + off) = __halves2bfloat162(l0, l1);
    }
}

// ---------------- host launcher ----------------
extern "C" void kernel_launch(void* const* d_in, const int* in_sizes, int n_in,
                              void* d_out, int out_size)
{
    const float* X    = (const float*)d_in[0];
    const int*   mask = (const int*)  d_in[1];
    const float* Wq   = (const float*)d_in[2];
    const float* bq   = (const float*)d_in[3];
    const float* Wk   = (const float*)d_in[4];
    const float* bk   = (const float*)d_in[5];
    const float* Wv   = (const float*)d_in[6];
    const float* bv   = (const float*)d_in[7];
    const float* Wo   = (const float*)d_in[8];
    const float* bo   = (const float*)d_in[9];
    const float* lnlg = (const float*)d_in[10];
    const float* lnlb = (const float*)d_in[11];
    const float* lnsg = (const float*)d_in[12];
    const float* lnsb = (const float*)d_in[13];
    const float* Wd   = (const float*)d_in[14];
    const float* bd   = (const float*)d_in[15];
    float* out = (float*)d_out;

    float *pQ,*pK,*pV,*pDl,*pKc,*pVc;
    cudaGetSymbolAddress((void**)&pQ,  g_Q);
    cudaGetSymbolAddress((void**)&pK,  g_K);
    cudaGetSymbolAddress((void**)&pV,  g_V);
    cudaGetSymbolAddress((void**)&pDl, g_Dl);
    cudaGetSymbolAddress((void**)&pKc, g_Kc);
    cudaGetSymbolAddress((void**)&pVc, g_Vc);
    __nv_bfloat16* bf;
    cudaGetSymbolAddress((void**)&bf, g_bf);

    static int attr_set = 0;
    if (!attr_set) {
        cudaFuncSetAttribute(attn_kernel, cudaFuncAttributeMaxDynamicSharedMemorySize, 92800);
        cudaFuncSetAttribute(gemm_mma_kernel, cudaFuncAttributeMaxDynamicSharedMemorySize, 65536);
        attr_set = 1;
    }

    const int M = BB*SSEQ;                       // 8192

    // bf16 splits + weight transposes
    split_kernel<<<2048,256>>>(X, bf+XHI, bf+XLO, M*HD);
    transpose_split_kernel<<<dim3(16,16),dim3(32,8)>>>(Wq, bf+WQTH, bf+WQTL, 512);
    transpose_split_kernel<<<dim3(16,16),dim3(32,8)>>>(Wk, bf+WKTH, bf+WKTL, 512);
    transpose_split_kernel<<<dim3(16,16),dim3(32,8)>>>(Wv, bf+WVTH, bf+WVTL, 512);
    transpose_split_kernel<<<dim3(32,16),dim3(32,8)>>>(Wd, bf+WDTH, bf+WDTL, 1024);
    transpose_split_kernel<<<dim3(16,16),dim3(32,8)>>>(Wo, bf+WOTH, bf+WOTL, 512);

    // projections on HMMA (Q carries the 1/sqrt(DH) scale)
    gemm_mma_kernel<<<dim3(4,64),256,65536>>>(bf+XHI, bf+XLO, bf+WQTH, bf+WQTL, bq, pQ,  512, 0.125f);
    gemm_mma_kernel<<<dim3(4,64),256,65536>>>(bf+XHI, bf+XLO, bf+WKTH, bf+WKTL, bk, pK,  512, 1.f);
    gemm_mma_kernel<<<dim3(4,64),256,65536>>>(bf+XHI, bf+XLO, bf+WVTH, bf+WVTL, bv, pV,  512, 1.f);
    gemm_mma_kernel<<<dim3(8,64),256,65536>>>(bf+XHI, bf+XLO, bf+WDTH, bf+WDTL, bd, pDl, 1024, 1.f);

    // ln_l on K, V
    ln512_kernel<<<M,128>>>(pK, lnlg, lnlb);
    ln512_kernel<<<M,128>>>(pV, lnlg, lnlb);

    // hs = softmax over sequence axis
    softmax_seq_kernel<<<dim3(HL/32, BB), dim3(32,32)>>>();

    // landmark Kc/Vc
    zero_kv_kernel<<<512,256>>>();
    landmark_kv_kernel<<<dim3(BB*NH, 8),256>>>();
    ln512_kernel<<<BB*LM,128>>>(pKc, lnsg, lnsb);
    ln512_kernel<<<BB*LM,128>>>(pVc, lnsg, lnsb);

    // fused long-short attention (writes bf16 hi/lo C directly)
    attn_kernel<<<dim3(SSEQ/QT, NH, BB), 256, 92800>>>(mask, bf+CHI, bf+CLO);

    // output projection on HMMA
    gemm_mma_kernel<<<dim3(4,64),256,65536>>>(bf+CHI, bf+CLO, bf+WOTH, bf+WOTL, bo, out, 512, 1.f);
}

// round 8
// speedup vs baseline: 1.2083x; 1.2083x over previous
#include <cuda_runtime.h>
#include <cuda_bf16.h>
#include <math.h>

#define BB 2
#define SSEQ 4096
#define NH 8
#define DHEAD 64
#define HD 512
#define LM 128
#define WWIN 128
#define EXTW 64
#define HL 1024
#define NKEY 384
#define QT 32

// ---------------- scratch (device globals; no allocations) ----------------
__device__ float g_Q [BB*SSEQ*HD];
__device__ float g_K [BB*SSEQ*HD];
__device__ float g_V [BB*SSEQ*HD];
__device__ float g_Dl[BB*SSEQ*HL];   // D logits, softmaxed in-place -> hs
__device__ float g_Kc[BB*LM*HD];
__device__ float g_Vc[BB*LM*HD];

// bf16 arena: X hi/lo, C hi/lo, transposed-weight hi/lo
#define XHI  0
#define XLO  4194304
#define CHI  8388608
#define CLO  12582912
#define WQTH 16777216
#define WQTL 17039360
#define WKTH 17301504
#define WKTL 17563648
#define WVTH 17825792
#define WVTL 18087936
#define WDTH 18350080
#define WDTL 18874368
#define WOTH 19398656
#define WOTL 19660800
__device__ __nv_bfloat16 g_bf[19922944];

// ================= helpers =================
__device__ __forceinline__ unsigned smem_u32(const void* p) {
    unsigned a;
    asm("{ .reg .u64 t; cvta.to.shared.u64 t, %1; cvt.u32.u64 %0, t; }" : "=r"(a) : "l"(p));
    return a;
}
__device__ __forceinline__ unsigned swz(unsigned b) { return b ^ ((b >> 3) & 0x70u); }

__device__ __forceinline__ void ldsm_x4(unsigned* r, unsigned addr) {
    asm volatile("ldmatrix.sync.aligned.m8n8.x4.shared.b16 {%0,%1,%2,%3}, [%4];"
        : "=r"(r[0]),"=r"(r[1]),"=r"(r[2]),"=r"(r[3]) : "r"(addr));
}
__device__ __forceinline__ void ldsm_x2(unsigned* r, unsigned addr) {
    asm volatile("ldmatrix.sync.aligned.m8n8.x2.shared.b16 {%0,%1}, [%2];"
        : "=r"(r[0]),"=r"(r[1]) : "r"(addr));
}
__device__ __forceinline__ void mma16816(float* c, const unsigned* a, const unsigned* b) {
    asm volatile("mma.sync.aligned.m16n8k16.row.col.f32.bf16.bf16.f32 "
        "{%0,%1,%2,%3}, {%4,%5,%6,%7}, {%8,%9}, {%0,%1,%2,%3};"
        : "+f"(c[0]),"+f"(c[1]),"+f"(c[2]),"+f"(c[3])
        : "r"(a[0]),"r"(a[1]),"r"(a[2]),"r"(a[3]), "r"(b[0]),"r"(b[1]));
}

// ================= bf16-split conversion kernels =================
__global__ __launch_bounds__(256) void split_kernel(
    const float* __restrict__ src, __nv_bfloat16* __restrict__ hi,
    __nv_bfloat16* __restrict__ lo, int n)
{
    int i = (blockIdx.x * 256 + threadIdx.x) * 8;
    if (i >= n) return;
    #pragma unroll
    for (int j = 0; j < 8; j += 4) {
        float4 v = *(const float4*)(src + i + j);
        __nv_bfloat16 h0 = __float2bfloat16(v.x);
        __nv_bfloat16 h1 = __float2bfloat16(v.y);
        __nv_bfloat16 h2 = __float2bfloat16(v.z);
        __nv_bfloat16 h3 = __float2bfloat16(v.w);
        __nv_bfloat16 l0 = __float2bfloat16(v.x - __bfloat162float(h0));
        __nv_bfloat16 l1 = __float2bfloat16(v.y - __bfloat162float(h1));
        __nv_bfloat16 l2 = __float2bfloat16(v.z - __bfloat162float(h2));
        __nv_bfloat16 l3 = __float2bfloat16(v.w - __bfloat162float(h3));
        *(__nv_bfloat162*)(hi + i + j)     = __halves2bfloat162(h0, h1);
        *(__nv_bfloat162*)(hi + i + j + 2) = __halves2bfloat162(h2, h3);
        *(__nv_bfloat162*)(lo + i + j)     = __halves2bfloat162(l0, l1);
        *(__nv_bfloat162*)(lo + i + j + 2) = __halves2bfloat162(l2, l3);
    }
}

// W [512, N] fp32 -> T hi/lo [N, 512] bf16
__global__ __launch_bounds__(256) void transpose_split_kernel(
    const float* __restrict__ W, __nv_bfloat16* __restrict__ Thi,
    __nv_bfloat16* __restrict__ Tlo, int N)
{
    __shared__ float tile[32][33];
    int n0 = blockIdx.x * 32, k0 = blockIdx.y * 32;
    int tx = threadIdx.x, ty = threadIdx.y;
    #pragma unroll
    for (int i = 0; i < 32; i += 8)
        tile[ty + i][tx] = W[(size_t)(k0 + ty + i) * N + n0 + tx];
    __syncthreads();
    #pragma unroll
    for (int i = 0; i < 32; i += 8) {
        float x = tile[tx][ty + i];
        __nv_bfloat16 h = __float2bfloat16(x);
        __nv_bfloat16 l = __float2bfloat16(x - __bfloat162float(h));
        size_t o = (size_t)(n0 + ty + i) * 512 + k0 + tx;
        Thi[o] = h; Tlo[o] = l;
    }
}

// ================= bf16-split GEMM on mma.sync (HMMA) =================
__device__ __forceinline__ void gemm_compute_stage(
    unsigned sb, int st, int wm, int wn, int lane, float acc[4][4][4])
{
    const unsigned sA = sb + (unsigned)st * 32768u;
    const unsigned sB = sA + 16384u;
    const int la = lane & 15;
    #pragma unroll
    for (int ks = 0; ks < 4; ++ks) {
        unsigned a[4][4], b[4][2];
        #pragma unroll
        for (int ma = 0; ma < 4; ++ma) {
            unsigned arow = (unsigned)(wm*64 + ma*16 + la);
            unsigned ab   = (unsigned)(ks*32 + ((lane>>4)&1)*16);
            ldsm_x4(a[ma], sA + swz(arow*128u + ab));
        }
        #pragma unroll
        for (int na = 0; na < 4; ++na) {
            unsigned brow = (unsigned)(wn*32 + na*8 + (la & 7));
            unsigned bb   = (unsigned)(ks*32 + ((la>>3)&1)*16);
            ldsm_x2(b[na], sB + swz(brow*128u + bb));
        }
        #pragma unroll
        for (int ma = 0; ma < 4; ++ma)
            #pragma unroll
            for (int na = 0; na < 4; ++na)
                mma16816(acc[ma][na], a[ma], b[na]);
    }
}

__global__ __launch_bounds__(256) void gemm_mma_kernel(
    const __nv_bfloat16* __restrict__ Ahi, const __nv_bfloat16* __restrict__ Alo,
    const __nv_bfloat16* __restrict__ Bhi, const __nv_bfloat16* __restrict__ Blo,
    const float* __restrict__ bias, float* __restrict__ C, int N, float alpha)
{
    extern __shared__ __align__(128) char smem[];
    const unsigned sb = smem_u32(smem);
    const int tid  = threadIdx.x;
    const int lane = tid & 31, wid = tid >> 5;
    const int wm = wid >> 2, wn = wid & 3;
    const int bm = blockIdx.y, bn = blockIdx.x;

    float acc[4][4][4];
    #pragma unroll
    for (int i=0;i<4;i++)
        #pragma unroll
        for (int j=0;j<4;j++)
            #pragma unroll
            for (int k=0;k<4;k++) acc[i][j][k]=0.f;

#define LDCH(rg, c) { \
    const __nv_bfloat16* As = ((c) >= 16) ? Alo : Ahi; \
    const __nv_bfloat16* Bs = ((c) >= 8 && (c) < 16) ? Blo : Bhi; \
    const int kc = (c) & 7; \
    _Pragma("unroll") \
    for (int i = 0; i < 4; ++i) { \
        int e = i*256 + tid; int r = e >> 3, u = e & 7; \
        (rg)[i]   = *(const uint4*)(As + (size_t)(bm*128 + r)*512 + kc*64 + u*8); \
        (rg)[4+i] = *(const uint4*)(Bs + (size_t)(bn*128 + r)*512 + kc*64 + u*8); \
    } }
#define STCH(st, rg) { \
    const unsigned base = (unsigned)(st) * 32768u; \
    _Pragma("unroll") \
    for (int i = 0; i < 4; ++i) { \
        int e = i*256 + tid; int r = e >> 3, u = e & 7; \
        unsigned off = swz((unsigned)(r*128 + u*16)); \
        *(uint4*)(smem + base + off)          = (rg)[i]; \
        *(uint4*)(smem + base + 16384u + off) = (rg)[4+i]; \
    } }

    {
        uint4 rg[8];
        LDCH(rg, 0);
        STCH(0, rg);
    }
    __syncthreads();

    for (int c = 0; c < 24; ++c) {
        uint4 rn[8];
        if (c < 23) LDCH(rn, c + 1);
        gemm_compute_stage(sb, c & 1, wm, wn, lane, acc);
        if (c < 23) STCH((c + 1) & 1, rn);
        __syncthreads();
    }
#undef LDCH
#undef STCH

    #pragma unroll
    for (int ma = 0; ma < 4; ++ma) {
        const int row = bm*128 + wm*64 + ma*16 + (lane >> 2);
        #pragma unroll
        for (int na = 0; na < 4; ++na) {
            const int col = bn*128 + wn*32 + na*8 + (lane & 3)*2;
            const float b0 = bias[col], b1 = bias[col+1];
            float2 o0, o1;
            o0.x = alpha*(acc[ma][na][0] + b0);
            o0.y = alpha*(acc[ma][na][1] + b1);
            o1.x = alpha*(acc[ma][na][2] + b0);
            o1.y = alpha*(acc[ma][na][3] + b1);
            *(float2*)(C + (size_t)row*N + col)       = o0;
            *(float2*)(C + (size_t)(row+8)*N + col)   = o1;
        }
    }
}

// ---------------- LayerNorm over rows of 512 (in-place) ----------------
__global__ __launch_bounds__(128) void ln512_kernel(
    float* __restrict__ Y, const float* __restrict__ gam, const float* __restrict__ bet)
{
    const int row = blockIdx.x;
    float* x = Y + (size_t)row * HD;
    const int t = threadIdx.x;
    float4 v = *(float4*)(x + t*4);
    float s  = v.x+v.y+v.z+v.w;
    float ss = v.x*v.x + v.y*v.y + v.z*v.z + v.w*v.w;
    #pragma unroll
    for (int o=16;o>0;o>>=1) {
        s  += __shfl_xor_sync(0xffffffffu, s, o);
        ss += __shfl_xor_sync(0xffffffffu, ss, o);
    }
    __shared__ float rs[4], rss[4];
    if ((t&31)==0) { rs[t>>5]=s; rss[t>>5]=ss; }
    __syncthreads();
    s  = rs[0]+rs[1]+rs[2]+rs[3];
    ss = rss[0]+rss[1]+rss[2]+rss[3];
    const float mean = s * (1.f/HD);
    const float var  = ss*(1.f/HD) - mean*mean;
    const float inv  = rsqrtf(var + 1e-5f);
    float4 g4 = *(const float4*)(gam + t*4);
    float4 b4 = *(const float4*)(bet + t*4);
    v.x = (v.x-mean)*inv*g4.x + b4.x;
    v.y = (v.y-mean)*inv*g4.y + b4.y;
    v.z = (v.z-mean)*inv*g4.z + b4.z;
    v.w = (v.w-mean)*inv*g4.w + b4.w;
    *(float4*)(x + t*4) = v;
}

// ---------------- softmax over sequence axis of g_Dl (B,S,HL), in-place ----------------
__global__ void softmax_seq_kernel()
{
    const int b = blockIdx.y;
    const int j = blockIdx.x*32 + threadIdx.x;
    const int ty = threadIdx.y;
    float m = -3.0e38f;
    for (int s = ty; s < SSEQ; s += 32)
        m = fmaxf(m, g_Dl[(size_t)(b*SSEQ+s)*HL + j]);
    __shared__ float sM[32][33];
    __shared__ float sS[32][33];
    sM[ty][threadIdx.x] = m;
    __syncthreads();
    float M = -3.0e38f;
    #pragma unroll
    for (int i=0;i<32;i++) M = fmaxf(M, sM[i][threadIdx.x]);
    float ssum = 0.f;
    for (int s = ty; s < SSEQ; s += 32)
        ssum += __expf(g_Dl[(size_t)(b*SSEQ+s)*HL + j] - M);
    sS[ty][threadIdx.x] = ssum;
    __syncthreads();
    float tot = 0.f;
    #pragma unroll
    for (int i=0;i<32;i++) tot += sS[i][threadIdx.x];
    const float inv = 1.f / tot;
    for (int s = ty; s < SSEQ; s += 32) {
        size_t off = (size_t)(b*SSEQ+s)*HL + j;
        g_Dl[off] = __expf(g_Dl[off] - M) * inv;
    }
}

// ---------------- zero Kc/Vc ----------------
__global__ void zero_kv_kernel()
{
    int i = blockIdx.x*256 + threadIdx.x;
    if (i < BB*LM*HD) { g_Kc[i]=0.f; g_Vc[i]=0.f; }
}

// ---------------- Kc = hs^T @ K, Vc = hs^T @ V (per b,h), split-K=8 with atomics ----------------
__global__ __launch_bounds__(256) void landmark_kv_kernel()
{
    const int b = blockIdx.x >> 3;
    const int h = blockIdx.x & 7;
    const int s0 = blockIdx.y * (SSEQ/8);
    __shared__ float sh[8][128];
    __shared__ float sk[8][64];
    __shared__ float sv[8][64];
    const int t = threadIdx.x;
    const int d  = t & 63;
    const int lg = t >> 6;
    float aK[32], aV[32];
    #pragma unroll
    for (int i=0;i<32;i++){aK[i]=0.f;aV[i]=0.f;}

    for (int sc = 0; sc < SSEQ/8; sc += 8) {
        #pragma unroll
        for (int u = 0; u < 8; ++u) {
            int idx = u*256 + t;
            int si = idx >> 8;
            int c  = idx & 255;
            int s  = s0 + sc + si;
            if (c < 128)      sh[si][c]     = g_Dl[(size_t)(b*SSEQ+s)*HL + h*LM + c];
            else if (c < 192) sk[si][c-128] = g_K [(size_t)(b*SSEQ+s)*HD + h*DHEAD + (c-128)];
            else              sv[si][c-192] = g_V [(size_t)(b*SSEQ+s)*HD + h*DHEAD + (c-192)];
        }
        __syncthreads();
        #pragma unroll
        for (int si=0; si<8; ++si) {
            const float kv = sk[si][d];
            const float vv = sv[si][d];
            const float4* hp = (const float4*)&sh[si][lg*32];
            #pragma unroll
            for (int i4=0;i4<8;i4++){
                float4 h4 = hp[i4];
                aK[i4*4+0] += h4.x*kv; aV[i4*4+0] += h4.x*vv;
                aK[i4*4+1] += h4.y*kv; aV[i4*4+1] += h4.y*vv;
                aK[i4*4+2] += h4.z*kv; aV[i4*4+2] += h4.z*vv;
                aK[i4*4+3] += h4.w*kv; aV[i4*4+3] += h4.w*vv;
            }
        }
        __syncthreads();
    }
    #pragma unroll
    for (int i=0;i<32;i++){
        const int l = lg*32 + i;
        atomicAdd(&g_Kc[(size_t)(b*LM+l)*HD + h*DHEAD + d], aK[i]);
        atomicAdd(&g_Vc[(size_t)(b*LM+l)*HD + h*DHEAD + d], aV[i]);
    }
}

// ---------------- fused attention (R6 layout): 6 key tiles of 64, softmax(384), PV ----------------
// Epilogue writes bf16 hi/lo split of C directly.
__global__ __launch_bounds__(256) void attn_kernel(
    const int* __restrict__ mask,
    __nv_bfloat16* __restrict__ Chi, __nv_bfloat16* __restrict__ Clo)
{
    extern __shared__ float smemf[];
    float* Qs  = smemf;             // 32*68
    float* Sc  = Qs + 32*68;        // 32*385 scores/probs
    float* KVs = Sc + 32*385;       // 64*68 key/value tile
    __shared__ int vld[64];

    const int b  = blockIdx.z;
    const int h  = blockIdx.y;
    const int q0 = blockIdx.x * QT;
    const int g  = q0 >> 7;
    const int t  = threadIdx.x;

    #pragma unroll
    for (int u=0; u<8; ++u) {
        int idx = u*256 + t;
        int q = idx >> 6, d = idx & 63;
        Qs[q*68+d] = g_Q[(size_t)(b*SSEQ+q0+q)*HD + h*DHEAD + d];
    }
    const int qg = t >> 3;
    const int kb = t & 7;

    for (int kt=0; kt<6; ++kt) {
        __syncthreads();
        if (t < 64) {
            int ok = 1;
            if (kt >= 2) {
                int p = g*WWIN - EXTW + (kt-2)*64 + t;
                ok = (p >= 0 && p < SSEQ) ? (mask[b*SSEQ+p] != 0) : 0;
            }
            vld[t] = ok;
        }
        #pragma unroll
        for (int u=0; u<16; ++u) {
            int idx = u*256 + t;
            int kk = idx >> 6, d = idx & 63;
            float val = 0.f;
            if (kt < 2) {
                val = g_Kc[(size_t)(b*LM + kt*64 + kk)*HD + h*DHEAD + d];
            } else {
                int p = g*WWIN - EXTW + (kt-2)*64 + kk;
                if (p >= 0 && p < SSEQ)
                    val = g_K[(size_t)(b*SSEQ+p)*HD + h*DHEAD + d];
            }
            KVs[kk*68+d] = val;
        }
        __syncthreads();

        float accv[8];
        #pragma unroll
        for (int j=0;j<8;j++) accv[j]=0.f;
        const float4* Qp = (const float4*)&Qs[qg*68];
        #pragma unroll
        for (int d4=0; d4<16; ++d4) {
            float4 qv = Qp[d4];
            #pragma unroll
            for (int j=0;j<8;j++) {
                float4 kv = *(const float4*)&KVs[(kb+8*j)*68 + d4*4];
                accv[j] += qv.x*kv.x + qv.y*kv.y + qv.z*kv.z + qv.w*kv.w;
            }
        }
        #pragma unroll
        for (int j=0;j<8;j++) {
            int k = kb + 8*j;
            Sc[qg*385 + kt*64 + k] = vld[k] ? accv[j] : -3.0e38f;
        }
    }
    __syncthreads();

    {
        float m = -3.0e38f;
        for (int k=kb; k<NKEY; k+=8) m = fmaxf(m, Sc[qg*385+k]);
        #pragma unroll
        for (int o=4;o>0;o>>=1) m = fmaxf(m, __shfl_xor_sync(0xffffffffu, m, o));
        float ssum = 0.f;
        for (int k=kb; k<NKEY; k+=8) {
            float e = __expf(Sc[qg*385+k] - m);
            Sc[qg*385+k] = e;
            ssum += e;
        }
        #pragma unroll
        for (int o=4;o>0;o>>=1) ssum += __shfl_xor_sync(0xffffffffu, ssum, o);
        float inv = (mask[b*SSEQ+q0+qg] != 0) ? (1.f/ssum) : 0.f;
        for (int k=kb; k<NKEY; k+=8) Sc[qg*385+k] *= inv;
    }

    float acc8[8];
    #pragma unroll
    for (int j=0;j<8;j++) acc8[j]=0.f;
    const int dq = kb;
    for (int kt=0; kt<6; ++kt) {
        __syncthreads();
        #pragma unroll
        for (int u=0; u<16; ++u) {
            int idx = u*256 + t;
            int kk = idx >> 6, d = idx & 63;
            float val = 0.f;
            if (kt < 2) {
                val = g_Vc[(size_t)(b*LM + kt*64 + kk)*HD + h*DHEAD + d];
            } else {
                int p = g*WWIN - EXTW + (kt-2)*64 + kk;
                if (p >= 0 && p < SSEQ)
                    val = g_V[(size_t)(b*SSEQ+p)*HD + h*DHEAD + d];
            }
            KVs[kk*68+d] = val;
        }
        __syncthreads();
        #pragma unroll 8
        for (int k=0; k<64; ++k) {
            float pv = Sc[qg*385 + kt*64 + k];
            float4 v0 = *(const float4*)&KVs[k*68 + dq*4];
            float4 v1 = *(const float4*)&KVs[k*68 + 32 + dq*4];
            acc8[0] += pv*v0.x; acc8[1] += pv*v0.y; acc8[2] += pv*v0.z; acc8[3] += pv*v0.w;
            acc8[4] += pv*v1.x; acc8[5] += pv*v1.y; acc8[6] += pv*v1.z; acc8[7] += pv*v1.w;
        }
    }

    // epilogue: bf16 hi/lo split of C written directly
    const size_t off = (size_t)(b*SSEQ+q0+qg)*HD + h*DHEAD;
    #pragma unroll
    for (int half = 0; half < 2; ++half) {
        const int dbase = half*32 + dq*4;
        float x0 = acc8[half*4+0], x1 = acc8[half*4+1];
        float x2 = acc8[half*4+2], x3 = acc8[half*4+3];
        __nv_bfloat16 h0 = __float2bfloat16(x0), h1 = __float2bfloat16(x1);
        __nv_bfloat16 h2 = __float2bfloat16(x2), h3 = __float2bfloat16(x3);
        __nv_bfloat16 l0 = __float2bfloat16(x0 - __bfloat162float(h0));
        __nv_bfloat16 l1 = __float2bfloat16(x1 - __bfloat162float(h1));
        __nv_bfloat16 l2 = __float2bfloat16(x2 - __bfloat162float(h2));
        __nv_bfloat16 l3 = __float2bfloat16(x3 - __bfloat162float(h3));
        *(__nv_bfloat162*)(Chi + off + dbase)     = __halves2bfloat162(h0, h1);
        *(__nv_bfloat162*)(Chi + off + dbase + 2) = __halves2bfloat162(h2, h3);
        *(__nv_bfloat162*)(Clo + off + dbase)     = __halves2bfloat162(l0, l1);
        *(__nv_bfloat162*)(Clo + off + dbase + 2) = __halves2bfloat162(l2, l3);
    }
}

// ---------------- host launcher ----------------
extern "C" void kernel_launch(void* const* d_in, const int* in_sizes, int n_in,
                              void* d_out, int out_size)
{
    const float* X    = (const float*)d_in[0];
    const int*   mask = (const int*)  d_in[1];
    const float* Wq   = (const float*)d_in[2];
    const float* bq   = (const float*)d_in[3];
    const float* Wk   = (const float*)d_in[4];
    const float* bk   = (const float*)d_in[5];
    const float* Wv   = (const float*)d_in[6];
    const float* bv   = (const float*)d_in[7];
    const float* Wo   = (const float*)d_in[8];
    const float* bo   = (const float*)d_in[9];
    const float* lnlg = (const float*)d_in[10];
    const float* lnlb = (const float*)d_in[11];
    const float* lnsg = (const float*)d_in[12];
    const float* lnsb = (const float*)d_in[13];
    const float* Wd   = (const float*)d_in[14];
    const float* bd   = (const float*)d_in[15];
    float* out = (float*)d_out;

    float *pQ,*pK,*pV,*pDl,*pKc,*pVc;
    cudaGetSymbolAddress((void**)&pQ,  g_Q);
    cudaGetSymbolAddress((void**)&pK,  g_K);
    cudaGetSymbolAddress((void**)&pV,  g_V);
    cudaGetSymbolAddress((void**)&pDl, g_Dl);
    cudaGetSymbolAddress((void**)&pKc, g_Kc);
    cudaGetSymbolAddress((void**)&pVc, g_Vc);
    __nv_bfloat16* bf;
    cudaGetSymbolAddress((void**)&bf, g_bf);

    static cudaStream_t s1, s2, s3;
    static cudaEvent_t evX, evK, evV, evD;
    static int init_done = 0;
    if (!init_done) {
        cudaFuncSetAttribute(attn_kernel, cudaFuncAttributeMaxDynamicSharedMemorySize, 75392);
        cudaFuncSetAttribute(gemm_mma_kernel, cudaFuncAttributeMaxDynamicSharedMemorySize, 65536);
        cudaStreamCreateWithFlags(&s1, cudaStreamNonBlocking);
        cudaStreamCreateWithFlags(&s2, cudaStreamNonBlocking);
        cudaStreamCreateWithFlags(&s3, cudaStreamNonBlocking);
        cudaEventCreateWithFlags(&evX, cudaEventDisableTiming);
        cudaEventCreateWithFlags(&evK, cudaEventDisableTiming);
        cudaEventCreateWithFlags(&evV, cudaEventDisableTiming);
        cudaEventCreateWithFlags(&evD, cudaEventDisableTiming);
        init_done = 1;
    }

    const int M = BB*SSEQ;                       // 8192
    cudaStream_t s0 = 0;

    // ---- s0: X split, then fork ----
    split_kernel<<<2048,256,0,s0>>>(X, bf+XHI, bf+XLO, M*HD);
    cudaEventRecord(evX, s0);

    // ---- s1: K branch ----
    transpose_split_kernel<<<dim3(16,16),dim3(32,8),0,s1>>>(Wk, bf+WKTH, bf+WKTL, 512);
    cudaStreamWaitEvent(s1, evX, 0);
    gemm_mma_kernel<<<dim3(4,64),256,65536,s1>>>(bf+XHI, bf+XLO, bf+WKTH, bf+WKTL, bk, pK, 512, 1.f);
    ln512_kernel<<<M,128,0,s1>>>(pK, lnlg, lnlb);
    cudaEventRecord(evK, s1);

    // ---- s2: V branch ----
    transpose_split_kernel<<<dim3(16,16),dim3(32,8),0,s2>>>(Wv, bf+WVTH, bf+WVTL, 512);
    cudaStreamWaitEvent(s2, evX, 0);
    gemm_mma_kernel<<<dim3(4,64),256,65536,s2>>>(bf+XHI, bf+XLO, bf+WVTH, bf+WVTL, bv, pV, 512, 1.f);
    ln512_kernel<<<M,128,0,s2>>>(pV, lnlg, lnlb);
    cudaEventRecord(evV, s2);

    // ---- s3: D branch (logits -> column softmax) ----
    transpose_split_kernel<<<dim3(32,16),dim3(32,8),0,s3>>>(Wd, bf+WDTH, bf+WDTL, 1024);
    cudaStreamWaitEvent(s3, evX, 0);
    gemm_mma_kernel<<<dim3(8,64),256,65536,s3>>>(bf+XHI, bf+XLO, bf+WDTH, bf+WDTL, bd, pDl, 1024, 1.f);
    softmax_seq_kernel<<<dim3(HL/32, BB), dim3(32,32),0,s3>>>();
    cudaEventRecord(evD, s3);

    // ---- s0: Q branch + Wo transpose + zero, then join ----
    transpose_split_kernel<<<dim3(16,16),dim3(32,8),0,s0>>>(Wq, bf+WQTH, bf+WQTL, 512);
    transpose_split_kernel<<<dim3(16,16),dim3(32,8),0,s0>>>(Wo, bf+WOTH, bf+WOTL, 512);
    gemm_mma_kernel<<<dim3(4,64),256,65536,s0>>>(bf+XHI, bf+XLO, bf+WQTH, bf+WQTL, bq, pQ, 512, 0.125f);
    zero_kv_kernel<<<512,256,0,s0>>>();
    cudaStreamWaitEvent(s0, evK, 0);
    cudaStreamWaitEvent(s0, evV, 0);
    cudaStreamWaitEvent(s0, evD, 0);

    // landmark Kc/Vc + short LN
    landmark_kv_kernel<<<dim3(BB*NH, 8),256,0,s0>>>();
    ln512_kernel<<<BB*LM,128,0,s0>>>(pKc, lnsg, lnsb);
    ln512_kernel<<<BB*LM,128,0,s0>>>(pVc, lnsg, lnsb);

    // fused long-short attention (writes bf16 hi/lo C directly)
    attn_kernel<<<dim3(SSEQ/QT, NH, BB), 256, 75392, s0>>>(mask, bf+CHI, bf+CLO);

    // output projection on HMMA
    gemm_mma_kernel<<<dim3(4,64),256,65536,s0>>>(bf+CHI, bf+CLO, bf+WOTH, bf+WOTL, bo, out, 512, 1.f);
}

// round 10
// speedup vs baseline: 1.2957x; 1.0723x over previous
#include <cuda_runtime.h>
#include <cuda_bf16.h>
#include <math.h>

#define BB 2
#define SSEQ 4096
#define NH 8
#define DHEAD 64
#define HD 512
#define LM 128
#define WWIN 128
#define EXTW 64
#define HL 1024
#define NKEY 384
#define QT 32

// ---------------- scratch (device globals; no allocations) ----------------
__device__ float g_Q [BB*SSEQ*HD];
__device__ float g_K [BB*SSEQ*HD];
__device__ float g_V [BB*SSEQ*HD];
__device__ float g_Dl[BB*SSEQ*HL];   // D logits, softmaxed in-place -> hs
__device__ float g_Kc[BB*LM*HD];
__device__ float g_Vc[BB*LM*HD];

// bf16 arena: X hi/lo, C hi/lo, transposed-weight hi/lo
#define XHI  0
#define XLO  4194304
#define CHI  8388608
#define CLO  12582912
#define WQTH 16777216
#define WQTL 17039360
#define WKTH 17301504
#define WKTL 17563648
#define WVTH 17825792
#define WVTL 18087936
#define WDTH 18350080
#define WDTL 18874368
#define WOTH 19398656
#define WOTL 19660800
__device__ __nv_bfloat16 g_bf[19922944];

// ================= helpers =================
__device__ __forceinline__ unsigned smem_u32(const void* p) {
    unsigned a;
    asm("{ .reg .u64 t; cvta.to.shared.u64 t, %1; cvt.u32.u64 %0, t; }" : "=r"(a) : "l"(p));
    return a;
}
__device__ __forceinline__ unsigned swz(unsigned b) { return b ^ ((b >> 3) & 0x70u); }

__device__ __forceinline__ void ldsm_x4(unsigned* r, unsigned addr) {
    asm volatile("ldmatrix.sync.aligned.m8n8.x4.shared.b16 {%0,%1,%2,%3}, [%4];"
        : "=r"(r[0]),"=r"(r[1]),"=r"(r[2]),"=r"(r[3]) : "r"(addr));
}
__device__ __forceinline__ void ldsm_x2(unsigned* r, unsigned addr) {
    asm volatile("ldmatrix.sync.aligned.m8n8.x2.shared.b16 {%0,%1}, [%2];"
        : "=r"(r[0]),"=r"(r[1]) : "r"(addr));
}
__device__ __forceinline__ void mma16816(float* c, const unsigned* a, const unsigned* b) {
    asm volatile("mma.sync.aligned.m16n8k16.row.col.f32.bf16.bf16.f32 "
        "{%0,%1,%2,%3}, {%4,%5,%6,%7}, {%8,%9}, {%0,%1,%2,%3};"
        : "+f"(c[0]),"+f"(c[1]),"+f"(c[2]),"+f"(c[3])
        : "r"(a[0]),"r"(a[1]),"r"(a[2]),"r"(a[3]), "r"(b[0]),"r"(b[1]));
}

// ================= bf16-split conversion kernels =================
__global__ __launch_bounds__(256) void split_kernel(
    const float* __restrict__ src, __nv_bfloat16* __restrict__ hi,
    __nv_bfloat16* __restrict__ lo, int n)
{
    int i = (blockIdx.x * 256 + threadIdx.x) * 8;
    if (i >= n) return;
    #pragma unroll
    for (int j = 0; j < 8; j += 4) {
        float4 v = *(const float4*)(src + i + j);
        __nv_bfloat16 h0 = __float2bfloat16(v.x);
        __nv_bfloat16 h1 = __float2bfloat16(v.y);
        __nv_bfloat16 h2 = __float2bfloat16(v.z);
        __nv_bfloat16 h3 = __float2bfloat16(v.w);
        __nv_bfloat16 l0 = __float2bfloat16(v.x - __bfloat162float(h0));
        __nv_bfloat16 l1 = __float2bfloat16(v.y - __bfloat162float(h1));
        __nv_bfloat16 l2 = __float2bfloat16(v.z - __bfloat162float(h2));
        __nv_bfloat16 l3 = __float2bfloat16(v.w - __bfloat162float(h3));
        *(__nv_bfloat162*)(hi + i + j)     = __halves2bfloat162(h0, h1);
        *(__nv_bfloat162*)(hi + i + j + 2) = __halves2bfloat162(h2, h3);
        *(__nv_bfloat162*)(lo + i + j)     = __halves2bfloat162(l0, l1);
        *(__nv_bfloat162*)(lo + i + j + 2) = __halves2bfloat162(l2, l3);
    }
}

// All 5 weights transposed+split in one launch.
// Tiles: [0,256) Wq, [256,512) Wk, [512,768) Wv, [768,1280) Wd, [1280,1536) Wo
__global__ __launch_bounds__(256) void transpose_split_all_kernel(
    const float* __restrict__ Wq, const float* __restrict__ Wk,
    const float* __restrict__ Wv, const float* __restrict__ Wd,
    const float* __restrict__ Wo, __nv_bfloat16* __restrict__ base)
{
    __shared__ float tile[32][33];
    const int id = blockIdx.x;
    const float* W; __nv_bfloat16 *Th, *Tl; int N, tl;
    if (id < 256)       { W = Wq; Th = base+WQTH; Tl = base+WQTL; N = 512;  tl = id; }
    else if (id < 512)  { W = Wk; Th = base+WKTH; Tl = base+WKTL; N = 512;  tl = id-256; }
    else if (id < 768)  { W = Wv; Th = base+WVTH; Tl = base+WVTL; N = 512;  tl = id-512; }
    else if (id < 1280) { W = Wd; Th = base+WDTH; Tl = base+WDTL; N = 1024; tl = id-768; }
    else                { W = Wo; Th = base+WOTH; Tl = base+WOTL; N = 512;  tl = id-1280; }
    const int nt = N >> 5;
    const int n0 = (tl % nt) * 32, k0 = (tl / nt) * 32;
    const int tx = threadIdx.x, ty = threadIdx.y;
    #pragma unroll
    for (int i = 0; i < 32; i += 8)
        tile[ty + i][tx] = W[(size_t)(k0 + ty + i) * N + n0 + tx];
    __syncthreads();
    #pragma unroll
    for (int i = 0; i < 32; i += 8) {
        float x = tile[tx][ty + i];
        __nv_bfloat16 h = __float2bfloat16(x);
        __nv_bfloat16 l = __float2bfloat16(x - __bfloat162float(h));
        size_t o = (size_t)(n0 + ty + i) * 512 + k0 + tx;
        Th[o] = h; Tl[o] = l;
    }
}

// ================= bf16-split GEMM core (mma.sync HMMA) =================
#define GEMM_CORE(Ahi, Alo, Bhi, Blo, Cptr, Nw, alphav, biasptr)                      \
{                                                                                      \
    float acc[4][4][4];                                                                \
    _Pragma("unroll")                                                                  \
    for (int i=0;i<4;i++) _Pragma("unroll") for (int j=0;j<4;j++)                      \
        _Pragma("unroll") for (int k=0;k<4;k++) acc[i][j][k]=0.f;                      \
    {                                                                                  \
        uint4 rg[8];                                                                   \
        _Pragma("unroll")                                                              \
        for (int i = 0; i < 4; ++i) {                                                  \
            int e = i*256 + tid; int r = e >> 3, u = e & 7;                            \
            rg[i]   = *(const uint4*)((Ahi) + (size_t)(bm*128 + r)*512 + u*8);         \
            rg[4+i] = *(const uint4*)((Bhi) + (size_t)(lbn*128 + r)*512 + u*8);        \
        }                                                                              \
        _Pragma("unroll")                                                              \
        for (int i = 0; i < 4; ++i) {                                                  \
            int e = i*256 + tid; int r = e >> 3, u = e & 7;                            \
            unsigned off = swz((unsigned)(r*128 + u*16));                              \
            *(uint4*)(smem + off)          = rg[i];                                    \
            *(uint4*)(smem + 16384u + off) = rg[4+i];                                  \
        }                                                                              \
    }                                                                                  \
    __syncthreads();                                                                   \
    for (int c = 0; c < 24; ++c) {                                                     \
        uint4 rn[8];                                                                   \
        if (c < 23) {                                                                  \
            const int cn = c + 1;                                                      \
            const __nv_bfloat16* As = (cn >= 16) ? (Alo) : (Ahi);                      \
            const __nv_bfloat16* Bs = (cn >= 8 && cn < 16) ? (Blo) : (Bhi);            \
            const int kc = cn & 7;                                                     \
            _Pragma("unroll")                                                          \
            for (int i = 0; i < 4; ++i) {                                              \
                int e = i*256 + tid; int r = e >> 3, u = e & 7;                        \
                rn[i]   = *(const uint4*)(As + (size_t)(bm*128 + r)*512 + kc*64 + u*8);\
                rn[4+i] = *(const uint4*)(Bs + (size_t)(lbn*128 + r)*512 + kc*64 + u*8);\
            }                                                                          \
        }                                                                              \
        gemm_compute_stage(sb, c & 1, wm, wn, lane, acc);                              \
        if (c < 23) {                                                                  \
            const unsigned basest = (unsigned)((c + 1) & 1) * 32768u;                  \
            _Pragma("unroll")                                                          \
            for (int i = 0; i < 4; ++i) {                                              \
                int e = i*256 + tid; int r = e >> 3, u = e & 7;                        \
                unsigned off = swz((unsigned)(r*128 + u*16));                          \
                *(uint4*)(smem + basest + off)          = rn[i];                       \
                *(uint4*)(smem + basest + 16384u + off) = rn[4+i];                     \
            }                                                                          \
        }                                                                              \
        __syncthreads();                                                               \
    }                                                                                  \
    _Pragma("unroll")                                                                  \
    for (int ma = 0; ma < 4; ++ma) {                                                   \
        const int row = bm*128 + wm*64 + ma*16 + (lane >> 2);                          \
        _Pragma("unroll")                                                              \
        for (int na = 0; na < 4; ++na) {                                               \
            const int col = lbn*128 + wn*32 + na*8 + (lane & 3)*2;                     \
            const float b0 = (biasptr)[col], b1 = (biasptr)[col+1];                    \
            float2 o0, o1;                                                             \
            o0.x = (alphav)*(acc[ma][na][0] + b0);                                     \
            o0.y = (alphav)*(acc[ma][na][1] + b1);                                     \
            o1.x = (alphav)*(acc[ma][na][2] + b0);                                     \
            o1.y = (alphav)*(acc[ma][na][3] + b1);                                     \
            *(float2*)((Cptr) + (size_t)row*(Nw) + col)     = o0;                      \
            *(float2*)((Cptr) + (size_t)(row+8)*(Nw) + col) = o1;                      \
        }                                                                              \
    }                                                                                  \
}

__device__ __forceinline__ void gemm_compute_stage(
    unsigned sb, int st, int wm, int wn, int lane, float acc[4][4][4])
{
    const unsigned sA = sb + (unsigned)st * 32768u;
    const unsigned sB = sA + 16384u;
    const int la = lane & 15;
    #pragma unroll
    for (int ks = 0; ks < 4; ++ks) {
        unsigned a[4][4], b[4][2];
        #pragma unroll
        for (int ma = 0; ma < 4; ++ma) {
            unsigned arow = (unsigned)(wm*64 + ma*16 + la);
            unsigned ab   = (unsigned)(ks*32 + ((lane>>4)&1)*16);
            ldsm_x4(a[ma], sA + swz(arow*128u + ab));
        }
        #pragma unroll
        for (int na = 0; na < 4; ++na) {
            unsigned brow = (unsigned)(wn*32 + na*8 + (la & 7));
            unsigned bb   = (unsigned)(ks*32 + ((la>>3)&1)*16);
            ldsm_x2(b[na], sB + swz(brow*128u + bb));
        }
        #pragma unroll
        for (int ma = 0; ma < 4; ++ma)
            #pragma unroll
            for (int na = 0; na < 4; ++na)
                mma16816(acc[ma][na], a[ma], b[na]);
    }
}

// generic single GEMM (used for the Wo projection)
__global__ __launch_bounds__(256) void gemm_mma_kernel(
    const __nv_bfloat16* __restrict__ Ahi, const __nv_bfloat16* __restrict__ Alo,
    const __nv_bfloat16* __restrict__ Bhi, const __nv_bfloat16* __restrict__ Blo,
    const float* __restrict__ bias, float* __restrict__ C, int N, float alpha)
{
    extern __shared__ __align__(128) char smem[];
    const unsigned sb = smem_u32(smem);
    const int tid  = threadIdx.x;
    const int lane = tid & 31, wid = tid >> 5;
    const int wm = wid >> 2, wn = wid & 3;
    const int bm = blockIdx.y, lbn = blockIdx.x;
    GEMM_CORE(Ahi, Alo, Bhi, Blo, C, N, alpha, bias);
}

// fused 4-projection GEMM: bn 0-3 Q, 4-7 K, 8-11 V, 12-19 D-logits
__global__ __launch_bounds__(256) void proj4_kernel(
    const __nv_bfloat16* __restrict__ Ahi, const __nv_bfloat16* __restrict__ Alo,
    const __nv_bfloat16* __restrict__ Qh, const __nv_bfloat16* __restrict__ Ql,
    const __nv_bfloat16* __restrict__ Kh, const __nv_bfloat16* __restrict__ Kl,
    const __nv_bfloat16* __restrict__ Vh, const __nv_bfloat16* __restrict__ Vl,
    const __nv_bfloat16* __restrict__ Dh, const __nv_bfloat16* __restrict__ Dlw,
    const float* __restrict__ bq, const float* __restrict__ bk,
    const float* __restrict__ bv, const float* __restrict__ bd,
    float* __restrict__ oQ, float* __restrict__ oK,
    float* __restrict__ oV, float* __restrict__ oD)
{
    extern __shared__ __align__(128) char smem[];
    const unsigned sb = smem_u32(smem);
    const int tid  = threadIdx.x;
    const int lane = tid & 31, wid = tid >> 5;
    const int wm = wid >> 2, wn = wid & 3;
    const int bm = blockIdx.y;
    const int bn = blockIdx.x;

    const __nv_bfloat16 *Bh, *Bl; const float* bias; float* Cp;
    int lbn, N; float alpha = 1.f;
    if (bn < 4)       { lbn = bn;    Bh = Qh; Bl = Ql;  bias = bq; Cp = oQ; N = 512; alpha = 0.125f; }
    else if (bn < 8)  { lbn = bn-4;  Bh = Kh; Bl = Kl;  bias = bk; Cp = oK; N = 512; }
    else if (bn < 12) { lbn = bn-8;  Bh = Vh; Bl = Vl;  bias = bv; Cp = oV; N = 512; }
    else              { lbn = bn-12; Bh = Dh; Bl = Dlw; bias = bd; Cp = oD; N = 1024; }
    GEMM_CORE(Ahi, Alo, Bh, Bl, Cp, N, alpha, bias);
}

// ---------------- LayerNorm over rows of 512, two tensors in one launch ----------------
__global__ __launch_bounds__(128) void ln512x2_kernel(
    float* __restrict__ Y1, float* __restrict__ Y2, int M1,
    const float* __restrict__ gam, const float* __restrict__ bet)
{
    const int row = blockIdx.x;
    float* x = (row < M1) ? (Y1 + (size_t)row * HD) : (Y2 + (size_t)(row - M1) * HD);
    const int t = threadIdx.x;
    float4 v = *(float4*)(x + t*4);
    float s  = v.x+v.y+v.z+v.w;
    float ss = v.x*v.x + v.y*v.y + v.z*v.z + v.w*v.w;
    #pragma unroll
    for (int o=16;o>0;o>>=1) {
        s  += __shfl_xor_sync(0xffffffffu, s, o);
        ss += __shfl_xor_sync(0xffffffffu, ss, o);
    }
    __shared__ float rs[4], rss[4];
    if ((t&31)==0) { rs[t>>5]=s; rss[t>>5]=ss; }
    __syncthreads();
    s  = rs[0]+rs[1]+rs[2]+rs[3];
    ss = rss[0]+rss[1]+rss[2]+rss[3];
    const float mean = s * (1.f/HD);
    const float var  = ss*(1.f/HD) - mean*mean;
    const float inv  = rsqrtf(var + 1e-5f);
    float4 g4 = *(const float4*)(gam + t*4);
    float4 b4 = *(const float4*)(bet + t*4);
    v.x = (v.x-mean)*inv*g4.x + b4.x;
    v.y = (v.y-mean)*inv*g4.y + b4.y;
    v.z = (v.z-mean)*inv*g4.z + b4.z;
    v.w = (v.w-mean)*inv*g4.w + b4.w;
    *(float4*)(x + t*4) = v;
}

// ---------------- softmax over sequence axis of g_Dl (B,S,HL), in-place ----------------
__global__ void softmax_seq_kernel()
{
    const int b = blockIdx.y;
    const int j = blockIdx.x*32 + threadIdx.x;
    const int ty = threadIdx.y;
    float m = -3.0e38f;
    for (int s = ty; s < SSEQ; s += 32)
        m = fmaxf(m, g_Dl[(size_t)(b*SSEQ+s)*HL + j]);
    __shared__ float sM[32][33];
    __shared__ float sS[32][33];
    sM[ty][threadIdx.x] = m;
    __syncthreads();
    float M = -3.0e38f;
    #pragma unroll
    for (int i=0;i<32;i++) M = fmaxf(M, sM[i][threadIdx.x]);
    float ssum = 0.f;
    for (int s = ty; s < SSEQ; s += 32)
        ssum += __expf(g_Dl[(size_t)(b*SSEQ+s)*HL + j] - M);
    sS[ty][threadIdx.x] = ssum;
    __syncthreads();
    float tot = 0.f;
    #pragma unroll
    for (int i=0;i<32;i++) tot += sS[i][threadIdx.x];
    const float inv = 1.f / tot;
    for (int s = ty; s < SSEQ; s += 32) {
        size_t off = (size_t)(b*SSEQ+s)*HL + j;
        g_Dl[off] = __expf(g_Dl[off] - M) * inv;
    }
}

// ---------------- zero Kc/Vc ----------------
__global__ void zero_kv_kernel()
{
    int i = blockIdx.x*256 + threadIdx.x;
    if (i < BB*LM*HD) { g_Kc[i]=0.f; g_Vc[i]=0.f; }
}

// ---------------- Kc = hs^T @ K, Vc = hs^T @ V (per b,h), split-K=8 with atomics ----------------
__global__ __launch_bounds__(256) void landmark_kv_kernel()
{
    const int b = blockIdx.x >> 3;
    const int h = blockIdx.x & 7;
    const int s0 = blockIdx.y * (SSEQ/8);
    __shared__ float sh[8][128];
    __shared__ float sk[8][64];
    __shared__ float sv[8][64];
    const int t = threadIdx.x;
    const int d  = t & 63;
    const int lg = t >> 6;
    float aK[32], aV[32];
    #pragma unroll
    for (int i=0;i<32;i++){aK[i]=0.f;aV[i]=0.f;}

    for (int sc = 0; sc < SSEQ/8; sc += 8) {
        #pragma unroll
        for (int u = 0; u < 8; ++u) {
            int idx = u*256 + t;
            int si = idx >> 8;
            int c  = idx & 255;
            int s  = s0 + sc + si;
            if (c < 128)      sh[si][c]     = g_Dl[(size_t)(b*SSEQ+s)*HL + h*LM + c];
            else if (c < 192) sk[si][c-128] = g_K [(size_t)(b*SSEQ+s)*HD + h*DHEAD + (c-128)];
            else              sv[si][c-192] = g_V [(size_t)(b*SSEQ+s)*HD + h*DHEAD + (c-192)];
        }
        __syncthreads();
        #pragma unroll
        for (int si=0; si<8; ++si) {
            const float kv = sk[si][d];
            const float vv = sv[si][d];
            const float4* hp = (const float4*)&sh[si][lg*32];
            #pragma unroll
            for (int i4=0;i4<8;i4++){
                float4 h4 = hp[i4];
                aK[i4*4+0] += h4.x*kv; aV[i4*4+0] += h4.x*vv;
                aK[i4*4+1] += h4.y*kv; aV[i4*4+1] += h4.y*vv;
                aK[i4*4+2] += h4.z*kv; aV[i4*4+2] += h4.z*vv;
                aK[i4*4+3] += h4.w*kv; aV[i4*4+3] += h4.w*vv;
            }
        }
        __syncthreads();
    }
    #pragma unroll
    for (int i=0;i<32;i++){
        const int l = lg*32 + i;
        atomicAdd(&g_Kc[(size_t)(b*LM+l)*HD + h*DHEAD + d], aK[i]);
        atomicAdd(&g_Vc[(size_t)(b*LM+l)*HD + h*DHEAD + d], aV[i]);
    }
}

// ---------------- fused attention: 6 key tiles of 64, softmax(384), PV, bf16 epilogue ----------------
__global__ __launch_bounds__(256) void attn_kernel(
    const int* __restrict__ mask,
    __nv_bfloat16* __restrict__ Chi, __nv_bfloat16* __restrict__ Clo)
{
    extern __shared__ float smemf[];
    float* Qs  = smemf;             // 32*68
    float* Sc  = Qs + 32*68;        // 32*385 scores/probs
    float* KVs = Sc + 32*385;       // 64*68 key/value tile
    __shared__ int vld[64];

    const int b  = blockIdx.z;
    const int h  = blockIdx.y;
    const int q0 = blockIdx.x * QT;
    const int g  = q0 >> 7;
    const int t  = threadIdx.x;

    #pragma unroll
    for (int u=0; u<8; ++u) {
        int idx = u*256 + t;
        int q = idx >> 6, d = idx & 63;
        Qs[q*68+d] = g_Q[(size_t)(b*SSEQ+q0+q)*HD + h*DHEAD + d];
    }
    const int qg = t >> 3;
    const int kb = t & 7;

    for (int kt=0; kt<6; ++kt) {
        __syncthreads();
        if (t < 64) {
            int ok = 1;
            if (kt >= 2) {
                int p = g*WWIN - EXTW + (kt-2)*64 + t;
                ok = (p >= 0 && p < SSEQ) ? (mask[b*SSEQ+p] != 0) : 0;
            }
            vld[t] = ok;
        }
        #pragma unroll
        for (int u=0; u<16; ++u) {
            int idx = u*256 + t;
            int kk = idx >> 6, d = idx & 63;
            float val = 0.f;
            if (kt < 2) {
                val = g_Kc[(size_t)(b*LM + kt*64 + kk)*HD + h*DHEAD + d];
            } else {
                int p = g*WWIN - EXTW + (kt-2)*64 + kk;
                if (p >= 0 && p < SSEQ)
                    val = g_K[(size_t)(b*SSEQ+p)*HD + h*DHEAD + d];
            }
            KVs[kk*68+d] = val;
        }
        __syncthreads();

        float accv[8];
        #pragma unroll
        for (int j=0;j<8;j++) accv[j]=0.f;
        const float4* Qp = (const float4*)&Qs[qg*68];
        #pragma unroll
        for (int d4=0; d4<16; ++d4) {
            float4 qv = Qp[d4];
            #pragma unroll
            for (int j=0;j<8;j++) {
                float4 kv = *(const float4*)&KVs[(kb+8*j)*68 + d4*4];
                accv[j] += qv.x*kv.x + qv.y*kv.y + qv.z*kv.z + qv.w*kv.w;
            }
        }
        #pragma unroll
        for (int j=0;j<8;j++) {
            int k = kb + 8*j;
            Sc[qg*385 + kt*64 + k] = vld[k] ? accv[j] : -3.0e38f;
        }
    }
    __syncthreads();

    {
        float m = -3.0e38f;
        for (int k=kb; k<NKEY; k+=8) m = fmaxf(m, Sc[qg*385+k]);
        #pragma unroll
        for (int o=4;o>0;o>>=1) m = fmaxf(m, __shfl_xor_sync(0xffffffffu, m, o));
        float ssum = 0.f;
        for (int k=kb; k<NKEY; k+=8) {
            float e = __expf(Sc[qg*385+k] - m);
            Sc[qg*385+k] = e;
            ssum += e;
        }
        #pragma unroll
        for (int o=4;o>0;o>>=1) ssum += __shfl_xor_sync(0xffffffffu, ssum, o);
        float inv = (mask[b*SSEQ+q0+qg] != 0) ? (1.f/ssum) : 0.f;
        for (int k=kb; k<NKEY; k+=8) Sc[qg*385+k] *= inv;
    }

    float acc8[8];
    #pragma unroll
    for (int j=0;j<8;j++) acc8[j]=0.f;
    const int dq = kb;
    for (int kt=0; kt<6; ++kt) {
        __syncthreads();
        #pragma unroll
        for (int u=0; u<16; ++u) {
            int idx = u*256 + t;
            int kk = idx >> 6, d = idx & 63;
            float val = 0.f;
            if (kt < 2) {
                val = g_Vc[(size_t)(b*LM + kt*64 + kk)*HD + h*DHEAD + d];
            } else {
                int p = g*WWIN - EXTW + (kt-2)*64 + kk;
                if (p >= 0 && p < SSEQ)
                    val = g_V[(size_t)(b*SSEQ+p)*HD + h*DHEAD + d];
            }
            KVs[kk*68+d] = val;
        }
        __syncthreads();
        #pragma unroll 8
        for (int k=0; k<64; ++k) {
            float pv = Sc[qg*385 + kt*64 + k];
            float4 v0 = *(const float4*)&KVs[k*68 + dq*4];
            float4 v1 = *(const float4*)&KVs[k*68 + 32 + dq*4];
            acc8[0] += pv*v0.x; acc8[1] += pv*v0.y; acc8[2] += pv*v0.z; acc8[3] += pv*v0.w;
            acc8[4] += pv*v1.x; acc8[5] += pv*v1.y; acc8[6] += pv*v1.z; acc8[7] += pv*v1.w;
        }
    }

    const size_t off = (size_t)(b*SSEQ+q0+qg)*HD + h*DHEAD;
    #pragma unroll
    for (int half = 0; half < 2; ++half) {
        const int dbase = half*32 + dq*4;
        float x0 = acc8[half*4+0], x1 = acc8[half*4+1];
        float x2 = acc8[half*4+2], x3 = acc8[half*4+3];
        __nv_bfloat16 h0 = __float2bfloat16(x0), h1 = __float2bfloat16(x1);
        __nv_bfloat16 h2 = __float2bfloat16(x2), h3 = __float2bfloat16(x3);
        __nv_bfloat16 l0 = __float2bfloat16(x0 - __bfloat162float(h0));
        __nv_bfloat16 l1 = __float2bfloat16(x1 - __bfloat162float(h1));
        __nv_bfloat16 l2 = __float2bfloat16(x2 - __bfloat162float(h2));
        __nv_bfloat16 l3 = __float2bfloat16(x3 - __bfloat162float(h3));
        *(__nv_bfloat162*)(Chi + off + dbase)     = __halves2bfloat162(h0, h1);
        *(__nv_bfloat162*)(Chi + off + dbase + 2) = __halves2bfloat162(h2, h3);
        *(__nv_bfloat162*)(Clo + off + dbase)     = __halves2bfloat162(l0, l1);
        *(__nv_bfloat162*)(Clo + off + dbase + 2) = __halves2bfloat162(l2, l3);
    }
}

// ---------------- host launcher (single stream) ----------------
extern "C" void kernel_launch(void* const* d_in, const int* in_sizes, int n_in,
                              void* d_out, int out_size)
{
    const float* X    = (const float*)d_in[0];
    const int*   mask = (const int*)  d_in[1];
    const float* Wq   = (const float*)d_in[2];
    const float* bq   = (const float*)d_in[3];
    const float* Wk   = (const float*)d_in[4];
    const float* bk   = (const float*)d_in[5];
    const float* Wv   = (const float*)d_in[6];
    const float* bv   = (const float*)d_in[7];
    const float* Wo   = (const float*)d_in[8];
    const float* bo   = (const float*)d_in[9];
    const float* lnlg = (const float*)d_in[10];
    const float* lnlb = (const float*)d_in[11];
    const float* lnsg = (const float*)d_in[12];
    const float* lnsb = (const float*)d_in[13];
    const float* Wd   = (const float*)d_in[14];
    const float* bd   = (const float*)d_in[15];
    float* out = (float*)d_out;

    float *pQ,*pK,*pV,*pDl,*pKc,*pVc;
    cudaGetSymbolAddress((void**)&pQ,  g_Q);
    cudaGetSymbolAddress((void**)&pK,  g_K);
    cudaGetSymbolAddress((void**)&pV,  g_V);
    cudaGetSymbolAddress((void**)&pDl, g_Dl);
    cudaGetSymbolAddress((void**)&pKc, g_Kc);
    cudaGetSymbolAddress((void**)&pVc, g_Vc);
    __nv_bfloat16* bf;
    cudaGetSymbolAddress((void**)&bf, g_bf);

    static int init_done = 0;
    if (!init_done) {
        cudaFuncSetAttribute(attn_kernel, cudaFuncAttributeMaxDynamicSharedMemorySize, 75392);
        cudaFuncSetAttribute(gemm_mma_kernel, cudaFuncAttributeMaxDynamicSharedMemorySize, 65536);
        cudaFuncSetAttribute(proj4_kernel, cudaFuncAttributeMaxDynamicSharedMemorySize, 65536);
        init_done = 1;
    }

    const int M = BB*SSEQ;                       // 8192

    // bf16 splits + all weight transposes (one launch)
    split_kernel<<<2048,256>>>(X, bf+XHI, bf+XLO, M*HD);
    transpose_split_all_kernel<<<1536,dim3(32,8)>>>(Wq, Wk, Wv, Wd, Wo, bf);

    // fused 4-projection GEMM (Q carries the 1/sqrt(DH) scale)
    proj4_kernel<<<dim3(20,64),256,65536>>>(
        bf+XHI, bf+XLO,
        bf+WQTH, bf+WQTL, bf+WKTH, bf+WKTL, bf+WVTH, bf+WVTL, bf+WDTH, bf+WDTL,
        bq, bk, bv, bd, pQ, pK, pV, pDl);

    // ln_l on K and V in one launch
    ln512x2_kernel<<<2*M,128>>>(pK, pV, M, lnlg, lnlb);

    // hs = softmax over sequence axis
    softmax_seq_kernel<<<dim3(HL/32, BB), dim3(32,32)>>>();

    // landmark Kc/Vc
    zero_kv_kernel<<<512,256>>>();
    landmark_kv_kernel<<<dim3(BB*NH, 8),256>>>();
    ln512x2_kernel<<<2*BB*LM,128>>>(pKc, pVc, BB*LM, lnsg, lnsb);

    // fused long-short attention (writes bf16 hi/lo C directly)
    attn_kernel<<<dim3(SSEQ/QT, NH, BB), 256, 75392>>>(mask, bf+CHI, bf+CLO);

    // output projection on HMMA
    gemm_mma_kernel<<<dim3(4,64),256,65536>>>(bf+CHI, bf+CLO, bf+WOTH, bf+WOTL, bo, out, 512, 1.f);
}